// round 1
// baseline (speedup 1.0000x reference)
#include <cuda_runtime.h>

// Shapes fixed by the benchmark problem.
#define Bb      8
#define CF      256
#define Hh      128
#define Ww      128
#define HL      512
#define WL      512
#define C_OLD   16
#define NPIX    (Bb * Hh * Ww)          // 131072

// Scratch in __device__ globals (no allocation allowed).
__device__ int   g_count;
__device__ int   g_list[NPIX];          // packed (pix << 5) | class_id
__device__ float g_sum[32];
__device__ int   g_cnt[32];

__global__ void k_init() {
    int t = threadIdx.x;
    if (t == 0) g_count = 0;
    if (t < 32) { g_sum[t] = 0.0f; g_cnt[t] = 0; }
}

// Phase 1: per downsampled pixel, gather label, if background compute argmax
// over 16 old-logit channels at the same (4h,4w) position; compact active
// (pseudo-class != 0) pixels into a list.
__global__ void k_phase1(const int* __restrict__ labels,
                         const float* __restrict__ outputs_old) {
    int pix = blockIdx.x * blockDim.x + threadIdx.x;
    if (pix >= NPIX) return;
    int b = pix >> 14;            // / (128*128)
    int h = (pix >> 7) & 127;
    int w = pix & 127;

    // nearest-down: src index = floor(i * 512/128) = 4*i
    int lab = labels[(b * HL + 4 * h) * WL + 4 * w];
    if (lab != 0) return;         // not background -> pseudo = 0 -> dropped class

    const float* p = outputs_old
                   + (size_t)b * C_OLD * HL * WL
                   + (size_t)(4 * h) * WL + 4 * w;
    float best = p[0];
    int id = 0;
    #pragma unroll
    for (int c = 1; c < C_OLD; ++c) {
        float v = p[(size_t)c * HL * WL];
        if (v > best) { best = v; id = c; }   // strict > keeps first-max (jnp.argmax)
    }
    if (id == 0) return;          // class 0 excluded from the final sum

    int pos = atomicAdd(&g_count, 1);
    g_list[pos] = (pix << 5) | id;
    atomicAdd(&g_cnt[id], 1);
}

// Phase 2: one warp per active pixel. Lane k accumulates channels k, k+32, ...
// (stride 128*128 floats). Warp-reduce, then one float atomic per pixel.
__global__ void k_phase2(const float* __restrict__ features,
                         const float* __restrict__ proto) {
    int lane   = threadIdx.x & 31;
    int warp   = (blockIdx.x * blockDim.x + threadIdx.x) >> 5;
    int nwarps = (gridDim.x * blockDim.x) >> 5;
    int count  = g_count;   // written by phase-1 kernel earlier in stream order

    for (int i = warp; i < count; i += nwarps) {
        int e   = g_list[i];
        int id  = e & 31;
        int pix = e >> 5;
        int b   = pix >> 14;
        int hw  = pix & 16383;

        const float* f  = features + (size_t)b * CF * Hh * Ww + hw;
        const float* pr = proto + id * CF;

        float acc = 0.0f;
        #pragma unroll
        for (int k = 0; k < CF / 32; ++k) {
            int c   = lane + 32 * k;
            float d = f[(size_t)c * Hh * Ww] - pr[c];
            acc += d * d;
        }
        #pragma unroll
        for (int o = 16; o; o >>= 1)
            acc += __shfl_xor_sync(0xffffffffu, acc, o);

        if (lane == 0)
            atomicAdd(&g_sum[id], acc * (1.0f / CF));
    }
}

__global__ void k_final(const int* __restrict__ classes_old,
                        const int* __restrict__ incremental_step,
                        float* __restrict__ out) {
    if (threadIdx.x != 0 || blockIdx.x != 0) return;
    if (*incremental_step == 0) { out[0] = 0.0f; return; }
    int nc = *classes_old;
    if (nc > 32) nc = 32;
    float r = 0.0f;
    for (int c = 1; c < nc; ++c)
        if (g_cnt[c] > 0) r += g_sum[c] / (float)g_cnt[c];
    out[0] = r;
}

extern "C" void kernel_launch(void* const* d_in, const int* in_sizes, int n_in,
                              void* d_out, int out_size) {
    // metadata order:
    // 0: outputs (unused)  1: outputs_old f32 [8,16,512,512]
    // 2: features f32 [8,256,128,128]  3: features_old (unused)
    // 4: labels i32 [8,512,512]  5: prototypes f32 [21,256]
    // 6: classes_old i32  7: incremental_step i32
    const float* outputs_old = (const float*)d_in[1];
    const float* features    = (const float*)d_in[2];
    const int*   labels      = (const int*)  d_in[4];
    const float* prototypes  = (const float*)d_in[5];
    const int*   classes_old = (const int*)  d_in[6];
    const int*   inc_step    = (const int*)  d_in[7];
    float* out = (float*)d_out;

    k_init<<<1, 64>>>();
    k_phase1<<<NPIX / 256, 256>>>(labels, outputs_old);
    k_phase2<<<1024, 256>>>(features, prototypes);
    k_final<<<1, 32>>>(classes_old, inc_step, out);
}

// round 2
// speedup vs baseline: 1.0703x; 1.0703x over previous
#include <cuda_runtime.h>

// Fixed problem shapes.
#define Bb      8
#define CF      256
#define Hh      128
#define Ww      128
#define HL      512
#define WL      512
#define C_OLD   16
#define NPIX    (Bb * Hh * Ww)          // 131072
#define NBLK    296                      // <= 152 SMs * occupancy 2 -> all co-resident
#define NTHR    256
#define NW      ((NBLK * NTHR) / 32)     // 2368 warps

// Scratch: zero at module load; the kernel re-zeroes everything it dirtied
// before exiting, so every invocation (correctness run, capture, replays)
// starts from the same state. No allocation anywhere.
__device__ int   g_count  = 0;
__device__ int   g_arrive = 0;
__device__ int   g_done   = 0;
__device__ int   g_list[NPIX];
__device__ float g_sum[32];
__device__ int   g_cnt[32];

__global__ void __launch_bounds__(NTHR, 2)
k_all(const int* __restrict__ labels,
      const float* __restrict__ outputs_old,
      const float* __restrict__ features,
      const float* __restrict__ proto,
      const int* __restrict__ classes_old,
      const int* __restrict__ inc_step,
      float* __restrict__ out)
{
    const int tid  = threadIdx.x;
    const int lane = tid & 31;
    const int gth  = blockIdx.x * NTHR + tid;

    // ---------------- Phase 1: labels gather + conditional argmax + compact ----------------
    // Loop bound NPIX and stride NBLK*NTHR: the trip-count boundary
    // (NPIX % (NBLK*NTHR) = 55296) is a multiple of 32, so all lanes of a warp
    // take the same number of iterations -> full-mask ballot is safe.
    for (int pix = gth; pix < NPIX; pix += NBLK * NTHR) {
        int b = pix >> 14;
        int h = (pix >> 7) & 127;
        int w = pix & 127;

        // nearest-down 512->128: src = 4*dst
        int lab = labels[(b * HL + 4 * h) * WL + 4 * w];
        int id = 0;
        if (lab == 0) {
            const float* p = outputs_old
                           + (size_t)b * C_OLD * HL * WL
                           + (size_t)(4 * h) * WL + 4 * w;
            float best = p[0];
            #pragma unroll
            for (int c = 1; c < C_OLD; ++c) {
                float v = p[(size_t)c * HL * WL];
                if (v > best) { best = v; id = c; }   // strict > = first-max (jnp.argmax)
            }
        }

        // warp-aggregated compaction of active (id != 0) pixels
        unsigned m = __ballot_sync(0xffffffffu, id != 0);
        if (m) {
            int leader = __ffs(m) - 1;
            int base;
            if (lane == leader) base = atomicAdd(&g_count, __popc(m));
            base = __shfl_sync(0xffffffffu, base, leader);
            if (id != 0) {
                int off = __popc(m & ((1u << lane) - 1));
                g_list[base + off] = (pix << 5) | id;
                atomicAdd(&g_cnt[id], 1);
            }
        }
    }

    // ---------------- Grid barrier (all 296 blocks co-resident) ----------------
    __threadfence();
    __syncthreads();
    if (tid == 0) {
        atomicAdd(&g_arrive, 1);
        while (atomicAdd(&g_arrive, 0) < NBLK) { __nanosleep(64); }
    }
    __syncthreads();
    __threadfence();

    // ---------------- Phase 2: warp-per-active-pixel 256-ch MSE ----------------
    const int count = g_count;
    const int gw    = gth >> 5;
    for (int i = gw; i < count; i += NW) {
        int e   = g_list[i];
        int id  = e & 31;
        int pix = e >> 5;
        int b   = pix >> 14;
        int hw  = pix & 16383;

        const float* f  = features + (size_t)b * CF * Hh * Ww + hw;
        const float* pr = proto + id * CF;

        float acc = 0.0f;
        #pragma unroll
        for (int k = 0; k < CF / 32; ++k) {
            int c   = lane + 32 * k;
            float d = f[(size_t)c * (Hh * Ww)] - pr[c];
            acc += d * d;
        }
        #pragma unroll
        for (int o = 16; o; o >>= 1)
            acc += __shfl_xor_sync(0xffffffffu, acc, o);
        if (lane == 0)
            atomicAdd(&g_sum[id], acc * (1.0f / CF));
    }

    // ---------------- Last-block finalize + scratch cleanup ----------------
    __threadfence();
    __syncthreads();
    __shared__ int s_ticket;
    if (tid == 0) s_ticket = atomicAdd(&g_done, 1);
    __syncthreads();
    if (s_ticket == NBLK - 1) {
        __threadfence();   // make all blocks' g_sum/g_cnt visible
        if (tid < 32) {
            int nc = *classes_old;
            if (nc > 32) nc = 32;
            float v = 0.0f;
            if (lane >= 1 && lane < nc && g_cnt[lane] > 0)
                v = g_sum[lane] / (float)g_cnt[lane];
            #pragma unroll
            for (int o = 16; o; o >>= 1)
                v += __shfl_xor_sync(0xffffffffu, v, o);
            if (lane == 0)
                out[0] = (*inc_step == 0) ? 0.0f : v;
        }
        __syncthreads();
        // reset scratch so the next invocation starts clean
        if (tid == 0) { g_count = 0; g_arrive = 0; g_done = 0; }
        if (tid < 32) { g_sum[tid] = 0.0f; g_cnt[tid] = 0; }
        __threadfence();
    }
}

extern "C" void kernel_launch(void* const* d_in, const int* in_sizes, int n_in,
                              void* d_out, int out_size) {
    // metadata order:
    // 0: outputs (unused)        1: outputs_old f32 [8,16,512,512]
    // 2: features f32 [8,256,128,128]   3: features_old (unused)
    // 4: labels i32 [8,512,512]  5: prototypes f32 [21,256]
    // 6: classes_old i32         7: incremental_step i32
    const float* outputs_old = (const float*)d_in[1];
    const float* features    = (const float*)d_in[2];
    const int*   labels      = (const int*)  d_in[4];
    const float* prototypes  = (const float*)d_in[5];
    const int*   classes_old = (const int*)  d_in[6];
    const int*   inc_step    = (const int*)  d_in[7];

    k_all<<<NBLK, NTHR>>>(labels, outputs_old, features, prototypes,
                          classes_old, inc_step, (float*)d_out);
}